// round 16
// baseline (speedup 1.0000x reference)
#include <cuda_runtime.h>
#include <cuda_bf16.h>
#include <math.h>
#include <stdint.h>

// Problem constants
#define BSZ   64
#define LSEQ  100
#define LP1   101
#define DIM   64
#define NCOL  (BSZ * LP1)   // 6464
#define NROW  (BSZ * LSEQ)  // 6400
#define NCOLP 6656          // padded compacted-col bound (52 * 128)
#define NDW   208           // dup-mask uint32 words per batch (6656/32)
#define NEG10K (-10000.0f)
#define LOG2E 1.4426950408889634f
#define NMT   50            // m-tiles
#define TOTAL_CTAS 296      // 148 SMs x 2 CTAs — every SM exactly 2, all resident
#define MAXP  6             // max worker CTAs per m-tile

// ---------------- scratch (__device__ globals; no allocs) ----------------
__device__ uint32_t g_dup32[BSZ * NDW];   // dup/pad bitmask per (batch, col)
__device__ uint4  g_Afrag4[NROW * 8];     // bf16(prec*log2e), m16n8k16 fragment order
__device__ uint4  g_Bfrag4[NCOLP * 8];    // bf16 compacted embs, fragment order
__device__ uint4  g_Bdeb4[52 * 256];      // 5th-K-step debias fragments per (ktile,cc,lane)
__device__ float  g_tgt[NROW];
__device__ float  g_partS[MAXP * NROW];   // [rank][row]
__device__ double g_rn[NMT];
__device__ double g_rd[NMT];
__device__ unsigned int g_bar;            // grid barrier counter (self-resetting)
__device__ unsigned int g_mctr[NMT];      // per-m-tile tickets (self-resetting)
__device__ unsigned int g_fin;            // finalizer ticket (self-resetting)

// ---------------- PTX helpers ----------------
__device__ __forceinline__ uint32_t smem_u32(const void* p) {
    uint32_t a;
    asm("{ .reg .u64 t; cvta.to.shared.u64 t, %1; cvt.u32.u64 %0, t; }" : "=r"(a) : "l"(p));
    return a;
}
__device__ __forceinline__ uint32_t pk2(float lo, float hi) {  // bf16x2, RN (unbiased)
    __nv_bfloat162 h = __floats2bfloat162_rn(lo, hi);
    return *(uint32_t*)&h;
}
__device__ __forceinline__ float ex2f(float x) {               // 2^x
    float y;
    asm("ex2.approx.f32 %0, %1;" : "=f"(y) : "f"(x));
    return y;
}
__device__ __forceinline__ void cp16(uint32_t dst, const void* src) {
    asm volatile("cp.async.ca.shared.global [%0], [%1], 16;" :: "r"(dst), "l"(src) : "memory");
}
#define CP_COMMIT()  asm volatile("cp.async.commit_group;" ::: "memory")
#define CP_WAIT0()   asm volatile("cp.async.wait_group 0;" ::: "memory")

__device__ __forceinline__ void mma16(float* c, uint4 a, uint32_t b0, uint32_t b1) {
    asm volatile("mma.sync.aligned.m16n8k16.row.col.f32.bf16.bf16.f32 "
        "{%0,%1,%2,%3}, {%4,%5,%6,%7}, {%8,%9}, {%0,%1,%2,%3};"
        : "+f"(c[0]), "+f"(c[1]), "+f"(c[2]), "+f"(c[3])
        : "r"(a.x), "r"(a.y), "r"(a.z), "r"(a.w), "r"(b0), "r"(b1));
}

// Grid-wide barrier (all 296 CTAs resident by construction).
__device__ __forceinline__ void gsync(unsigned int target) {
    __threadfence();
    __syncthreads();
    if (threadIdx.x == 0) {
        atomicAdd(&g_bar, 1u);
        while (*(volatile unsigned int*)&g_bar < target) { __nanosleep(32); }
    }
    __syncthreads();
}

// Local (per-CTA) compacted-column map into smem; returns nv. 512 threads.
__device__ __forceinline__ int local_compact(const int* __restrict__ log_mask,
                                             int* colid_s) {
    __shared__ int cnt[64];
    __shared__ int off[64];
    __shared__ int s_nv;
    int t = threadIdx.x, w = t >> 5, lane = t & 31;
    #pragma unroll
    for (int s = 0; s < 4; s++) {
        int b = 4 * w + s;
        int c = 0;
        #pragma unroll
        for (int ch = 0; ch < 4; ch++) {
            int pos = ch * 32 + lane;
            int flag = 0;
            if (pos <= LSEQ) flag = (pos == LSEQ) ? 1 : (log_mask[b * LSEQ + pos] != 0);
            c += __popc(__ballot_sync(0xffffffffu, flag));
        }
        if (lane == 0) cnt[b] = c;
    }
    __syncthreads();
    if (w == 0) {
        int c0 = cnt[2 * lane], c1 = cnt[2 * lane + 1];
        int s = c0 + c1, sc = s;
        #pragma unroll
        for (int o = 1; o < 32; o <<= 1) {
            int u = __shfl_up_sync(0xffffffffu, sc, o);
            if (lane >= o) sc += u;
        }
        int base = sc - s;
        off[2 * lane] = base;
        off[2 * lane + 1] = base + c0;
        if (lane == 31) s_nv = sc;
    }
    __syncthreads();
    #pragma unroll
    for (int s = 0; s < 4; s++) {
        int b = 4 * w + s;
        int o = off[b];
        #pragma unroll
        for (int ch = 0; ch < 4; ch++) {
            int pos = ch * 32 + lane;
            int flag = 0;
            if (pos <= LSEQ) flag = (pos == LSEQ) ? 1 : (log_mask[b * LSEQ + pos] != 0);
            unsigned bal = __ballot_sync(0xffffffffu, flag);
            if (flag)
                colid_s[o + __popc(bal & ((1u << lane) - 1u))] = b * LP1 + pos;
            o += __popc(bal);
        }
    }
    __syncthreads();
    return s_nv;
}

// Quick nv (for CTAs that don't need the column map).
__device__ __forceinline__ int local_nv(const int* __restrict__ log_mask) {
    __shared__ int acc[16];
    __shared__ int s_nv2;
    int t = threadIdx.x, w = t >> 5, lane = t & 31;
    int c = 0;
    for (int i = t; i < NROW; i += 512) c += (log_mask[i] != 0);
    #pragma unroll
    for (int o = 16; o > 0; o >>= 1) c += __shfl_down_sync(0xffffffffu, c, o);
    if (lane == 0) acc[w] = c;
    __syncthreads();
    if (t == 0) {
        int s = 0;
        #pragma unroll
        for (int i = 0; i < 16; i++) s += acc[i];
        s_nv2 = s + BSZ;
    }
    __syncthreads();
    return s_nv2;
}

// ---------------------------------------------------------------------------
// Megakernel: merged prep -> ONE gsync -> sync-free GEMM (K=80: 64 data +
// 16-slot debias fold; dup via bitmask in epilogue) -> distributed finalize.
// ---------------------------------------------------------------------------
#define SMEM_BYTES 66560
#define HEMPTY 0xFFFFFFFFu

__global__ __launch_bounds__(512, 2)
void mega_kernel(const int* __restrict__ log_mask,
                 const int* __restrict__ items,
                 const float* __restrict__ pop,
                 const float* __restrict__ prec,
                 const float* __restrict__ embs,
                 float* __restrict__ out) {
    extern __shared__ float sm[];
    const int t = threadIdx.x;
    const int cta = blockIdx.x;

    // ======================= Merged prep phase =======================
    int nv;
    if (cta < 116) {
        int* colid_s = (int*)sm;            // 6464 ints (26KB)
        nv = local_compact(log_mask, colid_s);
        if (cta < BSZ) {
            // ---- dup bitmask via 256-slot hash set; batch `cta` ----
            __shared__ uint32_t tab[256];
            int i = cta;
            if (t < 256) tab[t] = HEMPTY;
            __syncthreads();
            if (t < LP1) {
                uint32_t id = (uint32_t)items[i * LP1 + t];
                uint32_t h = (id * 2654435761u) >> 24;
                while (true) {
                    uint32_t old = atomicCAS((unsigned int*)&tab[h], HEMPTY, id);
                    if (old == HEMPTY || old == id) break;
                    h = (h + 1) & 255;
                }
            }
            __syncthreads();
            int nvp = (nv + 127) & ~127;
            int w = t >> 5, lane = t & 31;
            for (int base = w * 32; base < nvp; base += 512) {
                int kv = base + lane;
                bool dupbit = true;               // padding cols masked
                if (kv < nv) {
                    uint32_t id = (uint32_t)items[colid_s[kv]];
                    uint32_t h = (id * 2654435761u) >> 24;
                    dupbit = false;
                    while (true) {
                        uint32_t k = tab[h];
                        if (k == id) { dupbit = true; break; }
                        if (k == HEMPTY) break;
                        h = (h + 1) & 255;
                    }
                }
                unsigned bal = __ballot_sync(0xffffffffu, dupbit);
                if (lane == 0) g_dup32[i * NDW + (base >> 5)] = bal;
            }
        } else {
            // ---- B fragments + debias fragments, one ktile per CTA ----
            int ktile = cta - BSZ;              // 0..51
            int kt128 = ktile * 128;
            float4* stage4 = (float4*)(sm + 8192);   // 32KB at byte 32768
            const float4* e4 = (const float4*)embs;
            const float4 z4 = make_float4(0.f, 0.f, 0.f, 0.f);
            #pragma unroll
            for (int it = 0; it < 4; it++) {
                int j = t + it * 512;            // 2048 float4s
                int col = j >> 4, q = j & 15;
                int gc = kt128 + col;
                stage4[j] = (gc < nv) ? e4[colid_s[gc] * 16 + q] : z4;
            }
            __syncthreads();
            const float* stage = (const float*)stage4;
            #pragma unroll
            for (int it = 0; it < 2; it++) {
                int j = t + it * 512;            // 1024 frag uint4s
                int lane = j & 31;
                int g = lane >> 2, tig = lane & 3;
                int kt = (j >> 5) & 3;
                int cc = (j >> 7) & 7;
                int k0 = kt * 16 + tig * 2;
                const float* e0 = stage + (cc * 16 + g) * 64;
                const float* e1 = e0 + 8 * 64;
                uint4 v;
                v.x = pk2(e0[k0], e0[k0 + 1]);
                v.y = pk2(e0[k0 + 8], e0[k0 + 9]);
                v.z = pk2(e1[k0], e1[k0 + 1]);
                v.w = pk2(e1[k0 + 8], e1[k0 + 9]);
                g_Bfrag4[ktile * 1024 + j] = v;
            }
            // debias (5th K-step) fragments: value -log2? no: +(-log2 pop)
            if (t < 256) {
                int lane = t & 31;
                int cc = t >> 5;
                int g = lane >> 2, tig = lane & 3;
                int c0 = kt128 + cc * 16 + g;
                int c1 = c0 + 8;
                float d0 = 0.f, d1 = 0.f;
                if (c0 < nv) d0 = -log2f(pop[items[colid_s[c0]]]);
                if (c1 < nv) d1 = -log2f(pop[items[colid_s[c1]]]);
                uint4 v = make_uint4(0u, 0u, 0u, 0u);
                if (tig == 0) { v.x = pk2(d0, 0.f); v.z = pk2(d1, 0.f); }
                g_Bdeb4[ktile * 256 + t] = v;
            }
        }
    } else if (cta < 166) {
        // ---- A fragments, one m-tile per CTA: stage coalesced, pack ----
        nv = local_nv(log_mask);
        int mt = cta - 116;                      // 0..49
        float4* stage4 = (float4*)(sm + 8192);
        const float4* p4 = (const float4*)prec;
        #pragma unroll
        for (int it = 0; it < 4; it++) {
            int j = t + it * 512;                // 2048 float4s, coalesced
            stage4[j] = p4[mt * 2048 + j];
        }
        __syncthreads();
        const float* stage = (const float*)stage4;
        #pragma unroll
        for (int it = 0; it < 2; it++) {
            int j = t + it * 512;
            int lane = j & 31;
            int g = lane >> 2, tig = lane & 3;
            int kt = (j >> 5) & 3;
            int b16 = (j >> 7) & 7;
            int k0 = kt * 16 + tig * 2;
            const float* ar = stage + (b16 * 16 + g) * 64;
            const float* ar8 = ar + 8 * 64;
            uint4 v;
            v.x = pk2(ar[k0] * LOG2E, ar[k0 + 1] * LOG2E);
            v.y = pk2(ar8[k0] * LOG2E, ar8[k0 + 1] * LOG2E);
            v.z = pk2(ar[k0 + 8] * LOG2E, ar[k0 + 9] * LOG2E);
            v.w = pk2(ar8[k0 + 8] * LOG2E, ar8[k0 + 9] * LOG2E);
            g_Afrag4[mt * 1024 + j] = v;
        }
    } else {
        // ---- target logits (exact fp32), 130 CTAs over 51200 slots ----
        nv = local_nv(log_mask);
        for (int slot = (cta - 166) * 512 + t; slot < NROW * 8; slot += 130 * 512) {
            int r = slot >> 3, sub = slot & 7;
            int i = r / LSEQ, j = r - i * LSEQ;
            int pos = j + 1;
            int valid = (pos == LSEQ) ? 1 : (log_mask[i * LSEQ + pos] != 0);
            int tc = i * LP1 + pos;
            const float4* p4 = (const float4*)(prec + r * DIM);
            const float4* e4 = (const float4*)(embs + tc * DIM);
            float4 a0 = p4[sub], b0 = e4[sub], a1 = p4[sub + 8], b1 = e4[sub + 8];
            float s = a0.x * b0.x + a0.y * b0.y + a0.z * b0.z + a0.w * b0.w
                    + a1.x * b1.x + a1.y * b1.y + a1.z * b1.z + a1.w * b1.w;
            s += __shfl_down_sync(0xffffffffu, s, 4);
            s += __shfl_down_sync(0xffffffffu, s, 2);
            s += __shfl_down_sync(0xffffffffu, s, 1);
            if (sub == 0) g_tgt[r] = valid ? (s - logf(pop[items[tc]])) : NEG10K;
        }
    }

    gsync(TOTAL_CTAS);

    // ======================= Phase C: sync-free GEMM + exp2 row-sums ==========
    uint4* As4 = (uint4*)sm;                                   // 16 KB
    float* sred = sm + 4096;                                   // [4][128]

    const int w = t >> 5, lane = t & 31;
    const int g = lane >> 2, tig = lane & 3;
    const int rg = w >> 2;
    const int wcol = w & 3;
    const int mt_ = cta % NMT;
    const int rnk = cta / NMT;                 // 0..5
    const int P = (mt_ < 46) ? 6 : 5;
    const int m0 = mt_ * 128;
    const int T = (nv + 127) >> 7;
    const int ntiles = (T > rnk) ? ((T - rnk + P - 1) / P) : 0;

    // batch index per (mti,h) row
    int bidx[2][2];
    #pragma unroll
    for (int mti = 0; mti < 2; mti++)
        #pragma unroll
        for (int h = 0; h < 2; h++)
            bidx[mti][h] = (m0 + rg * 32 + mti * 16 + g + h * 8) / LSEQ;

    // A's constant 5th-K-step fragment: 1.0 at k=64 (tig==0 lanes only)
    uint4 a4;
    a4.x = (tig == 0) ? 0x00003F80u : 0u;
    a4.y = a4.x;
    a4.z = 0u; a4.w = 0u;

    float rs[4] = {0.f, 0.f, 0.f, 0.f};

    if (ntiles > 0) {
        // stage A once
        {
            const uint4* Ag = g_Afrag4 + (size_t)mt_ * 1024;
            cp16(smem_u32(sm) + t * 16, Ag + t);
            cp16(smem_u32(sm) + (t + 512) * 16, Ag + t + 512);
            CP_COMMIT();
            CP_WAIT0();
            __syncthreads();
        }
        const uint4* a0p = As4 + (rg * 2 + 0) * 128 + lane;
        const uint4* a1p = As4 + (rg * 2 + 1) * 128 + lane;

        for (int ti = 0; ti < ntiles; ti++) {
            const int ktile = rnk + ti * P;
            const uint4* bt = g_Bfrag4 + (size_t)ktile * 1024;
            const uint4* bdt = g_Bdeb4 + ktile * 256;
            const int mw = ktile * 4 + wcol;

            // dup masks for this tile (one uint32 per row-group)
            uint32_t msk[2][2];
            #pragma unroll
            for (int mti = 0; mti < 2; mti++)
                #pragma unroll
                for (int h = 0; h < 2; h++)
                    msk[mti][h] = __ldg(g_dup32 + bidx[mti][h] * NDW + mw);

            #pragma unroll
            for (int cc2 = 0; cc2 < 2; cc2++) {
                const int cc = wcol * 2 + cc2;
                const uint4* bp = bt + cc * 128 + lane;
                uint4 b0 = __ldg(bp);
                uint4 b1 = __ldg(bp + 32);
                uint4 b2 = __ldg(bp + 64);
                uint4 b3 = __ldg(bp + 96);
                uint4 bd = __ldg(bdt + cc * 32 + lane);

                float c[2][2][4];
                #pragma unroll
                for (int mti = 0; mti < 2; mti++)
                    #pragma unroll
                    for (int nt = 0; nt < 2; nt++)
                        #pragma unroll
                        for (int q = 0; q < 4; q++) c[mti][nt][q] = 0.f;

                {
                    uint4 a0 = a0p[0],  a1 = a1p[0];
                    mma16(c[0][0], a0, b0.x, b0.y); mma16(c[0][1], a0, b0.z, b0.w);
                    mma16(c[1][0], a1, b0.x, b0.y); mma16(c[1][1], a1, b0.z, b0.w);
                }
                {
                    uint4 a0 = a0p[32], a1 = a1p[32];
                    mma16(c[0][0], a0, b1.x, b1.y); mma16(c[0][1], a0, b1.z, b1.w);
                    mma16(c[1][0], a1, b1.x, b1.y); mma16(c[1][1], a1, b1.z, b1.w);
                }
                {
                    uint4 a0 = a0p[64], a1 = a1p[64];
                    mma16(c[0][0], a0, b2.x, b2.y); mma16(c[0][1], a0, b2.z, b2.w);
                    mma16(c[1][0], a1, b2.x, b2.y); mma16(c[1][1], a1, b2.z, b2.w);
                }
                {
                    uint4 a0 = a0p[96], a1 = a1p[96];
                    mma16(c[0][0], a0, b3.x, b3.y); mma16(c[0][1], a0, b3.z, b3.w);
                    mma16(c[1][0], a1, b3.x, b3.y); mma16(c[1][1], a1, b3.z, b3.w);
                }
                // debias fold (k=64..79): A slice is constant 1.0 at k=64
                mma16(c[0][0], a4, bd.x, bd.y); mma16(c[0][1], a4, bd.z, bd.w);
                mma16(c[1][0], a4, bd.x, bd.y); mma16(c[1][1], a4, bd.z, bd.w);

                // epilogue: ex2 with dup-bit suppression
                #pragma unroll
                for (int mti = 0; mti < 2; mti++) {
                    #pragma unroll
                    for (int nt = 0; nt < 2; nt++) {
                        int p0 = cc2 * 16 + nt * 8 + 2 * tig;
                        uint32_t m0b = msk[mti][0], m1b = msk[mti][1];
                        if (!((m0b >> p0) & 1u))       rs[mti * 2 + 0] += ex2f(c[mti][nt][0]);
                        if (!((m0b >> (p0 + 1)) & 1u)) rs[mti * 2 + 0] += ex2f(c[mti][nt][1]);
                        if (!((m1b >> p0) & 1u))       rs[mti * 2 + 1] += ex2f(c[mti][nt][2]);
                        if (!((m1b >> (p0 + 1)) & 1u)) rs[mti * 2 + 1] += ex2f(c[mti][nt][3]);
                    }
                }
            }
        }
    }

    // in-CTA: reduce 4 tig lanes, then 4 col-group slices
    #pragma unroll
    for (int q = 0; q < 4; q++) {
        rs[q] += __shfl_xor_sync(0xffffffffu, rs[q], 1);
        rs[q] += __shfl_xor_sync(0xffffffffu, rs[q], 2);
    }
    __syncthreads();   // A smem / sred reuse ordering
    if (tig == 0) {
        #pragma unroll
        for (int mti = 0; mti < 2; mti++)
            #pragma unroll
            for (int h = 0; h < 2; h++)
                sred[wcol * 128 + rg * 32 + mti * 16 + h * 8 + g] = rs[mti * 2 + h];
    }
    __syncthreads();
    if (t < 128) {
        float s = (sred[t] + sred[t + 128]) + (sred[t + 256] + sred[t + 384]);
        g_partS[rnk * NROW + m0 + t] = s;
    }

    // ============== Phase D: per-m-tile finalize + deterministic total ==============
    __shared__ unsigned int s_lastm;
    __threadfence();
    __syncthreads();
    if (t == 0)
        s_lastm = (atomicAdd(&g_mctr[mt_], 1u) == (unsigned)(P - 1)) ? 1u : 0u;
    __syncthreads();
    if (s_lastm) {
        __threadfence();
        double num = 0.0, den = 0.0;
        if (t < 128) {
            int r = m0 + t;
            float S = 0.f;
            for (int c = 0; c < P; c++) S += g_partS[c * NROW + r];
            float tv = g_tgt[r];
            S += __expf(tv);
            float nll = (S > 0.f) ? (logf(S) - tv) : logf((float)NCOL);
            if (log_mask[r] != 0) { num = (double)nll; den = 1.0; }
        }
        #pragma unroll
        for (int o = 16; o > 0; o >>= 1) {
            num += __shfl_down_sync(0xffffffffu, num, o);
            den += __shfl_down_sync(0xffffffffu, den, o);
        }
        __shared__ double swn[16];
        __shared__ double swd[16];
        if (lane == 0) { swn[w] = num; swd[w] = den; }
        __syncthreads();
        if (t == 0) {
            double n = 0.0, d = 0.0;
            #pragma unroll
            for (int i = 0; i < 4; i++) { n += swn[i]; d += swd[i]; }
            g_rn[mt_] = n;
            g_rd[mt_] = d;
            __threadfence();
            if (atomicAdd(&g_fin, 1u) == NMT - 1) {
                __threadfence();
                double tn = 0.0, td = 0.0;
                for (int i = 0; i < NMT; i++) { tn += g_rn[i]; td += g_rd[i]; }
                out[0] = (float)(tn / td);
                // self-reset for next graph replay
                for (int i = 0; i < NMT; i++) g_mctr[i] = 0u;
                g_fin = 0u;
                g_bar = 0u;
            }
        }
    }
}

// ---------------------------------------------------------------------------
extern "C" void kernel_launch(void* const* d_in, const int* in_sizes, int n_in,
                              void* d_out, int out_size) {
    const float* prec  = (const float*)d_in[0];  // [6400, 64]
    const float* embs  = (const float*)d_in[1];  // [6464, 64]
    const float* pop   = (const float*)d_in[2];  // [100001]
    const int*   items = (const int*)d_in[3];    // [6464]
    const int*   lmask = (const int*)d_in[4];    // [64, 100]
    float* out = (float*)d_out;

    cudaFuncSetAttribute(mega_kernel, cudaFuncAttributeMaxDynamicSharedMemorySize,
                         SMEM_BYTES);

    mega_kernel<<<TOTAL_CTAS, 512, SMEM_BYTES>>>(lmask, items, pop, prec, embs, out);
}

// round 17
// speedup vs baseline: 1.3653x; 1.3653x over previous
#include <cuda_runtime.h>
#include <cuda_bf16.h>
#include <math.h>
#include <stdint.h>

// Problem constants
#define BSZ   64
#define LSEQ  100
#define LP1   101
#define DIM   64
#define NCOL  (BSZ * LP1)   // 6464
#define NROW  (BSZ * LSEQ)  // 6400
#define NCOLP 6656          // padded compacted-col bound (52 * 128)
#define NEG10K (-10000.0f)
#define LOG2E 1.4426950408889634f
#define NMT   50            // m-tiles
#define TOTAL_CTAS 296      // 148 SMs x 2 CTAs — every SM exactly 2, all resident
#define MAXP  6             // max worker CTAs per m-tile

// ---------------- scratch (__device__ globals; no allocs) ----------------
__device__ float  g_keep[BSZ * NCOLP];    // -log2(pop) or -inf per (batch, padded col)
__device__ uint4  g_Afrag4[NROW * 8];     // bf16(prec*log2e), m16n8k16 fragment order
__device__ uint4  g_Bfrag4[NCOLP * 8];    // bf16 compacted embs, fragment order
__device__ float  g_tgt[NROW];
__device__ float  g_partS[MAXP * NROW];   // [rank][row]
__device__ double g_rn[NMT];
__device__ double g_rd[NMT];
__device__ unsigned int g_bar;            // grid barrier counter (self-resetting)
__device__ unsigned int g_mctr[NMT];      // per-m-tile tickets (self-resetting)
__device__ unsigned int g_fin;            // finalizer ticket (self-resetting)

// ---------------- PTX helpers ----------------
__device__ __forceinline__ uint32_t smem_u32(const void* p) {
    uint32_t a;
    asm("{ .reg .u64 t; cvta.to.shared.u64 t, %1; cvt.u32.u64 %0, t; }" : "=r"(a) : "l"(p));
    return a;
}
__device__ __forceinline__ uint32_t pk2(float lo, float hi) {  // bf16x2, RN (unbiased)
    __nv_bfloat162 h = __floats2bfloat162_rn(lo, hi);
    return *(uint32_t*)&h;
}
__device__ __forceinline__ float ex2f(float x) {               // 2^x, -inf -> 0
    float y;
    asm("ex2.approx.f32 %0, %1;" : "=f"(y) : "f"(x));
    return y;
}
__device__ __forceinline__ void cp16(uint32_t dst, const void* src) {
    asm volatile("cp.async.ca.shared.global [%0], [%1], 16;" :: "r"(dst), "l"(src) : "memory");
}
#define CP_COMMIT()  asm volatile("cp.async.commit_group;" ::: "memory")
#define CP_WAIT0()   asm volatile("cp.async.wait_group 0;" ::: "memory")

__device__ __forceinline__ void mma16(float* c, uint4 a, uint32_t b0, uint32_t b1) {
    asm volatile("mma.sync.aligned.m16n8k16.row.col.f32.bf16.bf16.f32 "
        "{%0,%1,%2,%3}, {%4,%5,%6,%7}, {%8,%9}, {%0,%1,%2,%3};"
        : "+f"(c[0]), "+f"(c[1]), "+f"(c[2]), "+f"(c[3])
        : "r"(a.x), "r"(a.y), "r"(a.z), "r"(a.w), "r"(b0), "r"(b1));
}

// Grid-wide barrier (all 296 CTAs resident by construction).
__device__ __forceinline__ void gsync(unsigned int target) {
    __threadfence();
    __syncthreads();
    if (threadIdx.x == 0) {
        atomicAdd(&g_bar, 1u);
        while (*(volatile unsigned int*)&g_bar < target) { __nanosleep(32); }
    }
    __syncthreads();
}

// Local (per-CTA) compacted-column map into smem; returns nv. 512 threads.
__device__ __forceinline__ int local_compact(const int* __restrict__ log_mask,
                                             int* colid_s) {
    __shared__ int cnt[64];
    __shared__ int off[64];
    __shared__ int s_nv;
    int t = threadIdx.x, w = t >> 5, lane = t & 31;
    #pragma unroll
    for (int s = 0; s < 4; s++) {
        int b = 4 * w + s;
        int c = 0;
        #pragma unroll
        for (int ch = 0; ch < 4; ch++) {
            int pos = ch * 32 + lane;
            int flag = 0;
            if (pos <= LSEQ) flag = (pos == LSEQ) ? 1 : (log_mask[b * LSEQ + pos] != 0);
            c += __popc(__ballot_sync(0xffffffffu, flag));
        }
        if (lane == 0) cnt[b] = c;
    }
    __syncthreads();
    if (w == 0) {
        int c0 = cnt[2 * lane], c1 = cnt[2 * lane + 1];
        int s = c0 + c1, sc = s;
        #pragma unroll
        for (int o = 1; o < 32; o <<= 1) {
            int u = __shfl_up_sync(0xffffffffu, sc, o);
            if (lane >= o) sc += u;
        }
        int base = sc - s;
        off[2 * lane] = base;
        off[2 * lane + 1] = base + c0;
        if (lane == 31) s_nv = sc;
    }
    __syncthreads();
    #pragma unroll
    for (int s = 0; s < 4; s++) {
        int b = 4 * w + s;
        int o = off[b];
        #pragma unroll
        for (int ch = 0; ch < 4; ch++) {
            int pos = ch * 32 + lane;
            int flag = 0;
            if (pos <= LSEQ) flag = (pos == LSEQ) ? 1 : (log_mask[b * LSEQ + pos] != 0);
            unsigned bal = __ballot_sync(0xffffffffu, flag);
            if (flag)
                colid_s[o + __popc(bal & ((1u << lane) - 1u))] = b * LP1 + pos;
            o += __popc(bal);
        }
    }
    __syncthreads();
    return s_nv;
}

// Quick nv (for CTAs that don't need the column map).
__device__ __forceinline__ int local_nv(const int* __restrict__ log_mask) {
    __shared__ int acc[16];
    __shared__ int s_nv2;
    int t = threadIdx.x, w = t >> 5, lane = t & 31;
    int c = 0;
    for (int i = t; i < NROW; i += 512) c += (log_mask[i] != 0);
    #pragma unroll
    for (int o = 16; o > 0; o >>= 1) c += __shfl_down_sync(0xffffffffu, c, o);
    if (lane == 0) acc[w] = c;
    __syncthreads();
    if (t == 0) {
        int s = 0;
        #pragma unroll
        for (int i = 0; i < 16; i++) s += acc[i];
        s_nv2 = s + BSZ;
    }
    __syncthreads();
    return s_nv2;
}

// ---------------------------------------------------------------------------
// Megakernel: merged prep -> ONE gsync -> sync-free GEMM (B + keep straight
// from L2, A in smem; mti processed sequentially to stay under 64 regs)
// -> distributed finalize.
// ---------------------------------------------------------------------------
#define SMEM_BYTES 66560
#define HEMPTY 0xFFFFFFFFu

__global__ __launch_bounds__(512, 2)
void mega_kernel(const int* __restrict__ log_mask,
                 const int* __restrict__ items,
                 const float* __restrict__ pop,
                 const float* __restrict__ prec,
                 const float* __restrict__ embs,
                 float* __restrict__ out) {
    extern __shared__ float sm[];
    const int t = threadIdx.x;
    const int cta = blockIdx.x;

    // ======================= Merged prep phase =======================
    int nv;
    if (cta < 116) {
        int* colid_s = (int*)sm;            // 6464 ints (26KB)
        nv = local_compact(log_mask, colid_s);
        if (cta < BSZ) {
            // ---- dup mask via 256-slot hash set; keep for batch `cta` ----
            __shared__ uint32_t tab[256];
            int i = cta;
            if (t < 256) tab[t] = HEMPTY;
            __syncthreads();
            if (t < LP1) {
                uint32_t id = (uint32_t)items[i * LP1 + t];
                uint32_t h = (id * 2654435761u) >> 24;
                while (true) {
                    uint32_t old = atomicCAS((unsigned int*)&tab[h], HEMPTY, id);
                    if (old == HEMPTY || old == id) break;
                    h = (h + 1) & 255;
                }
            }
            __syncthreads();
            int nvp = (nv + 127) & ~127;
            const float NINF = __int_as_float(0xff800000);
            for (int kv = t; kv < nvp; kv += 512) {
                float o = NINF;
                if (kv < nv) {
                    uint32_t id = (uint32_t)items[colid_s[kv]];
                    uint32_t h = (id * 2654435761u) >> 24;
                    bool dup = false;
                    while (true) {
                        uint32_t k = tab[h];
                        if (k == id) { dup = true; break; }
                        if (k == HEMPTY) break;
                        h = (h + 1) & 255;
                    }
                    o = dup ? NINF : -log2f(pop[id]);
                }
                g_keep[i * NCOLP + kv] = o;
            }
        } else {
            // ---- B fragments, one ktile per CTA: stage coalesced, pack ----
            int ktile = cta - BSZ;              // 0..51
            int kt128 = ktile * 128;
            float4* stage4 = (float4*)(sm + 8192);   // 32KB at byte 32768
            const float4* e4 = (const float4*)embs;
            const float4 z4 = make_float4(0.f, 0.f, 0.f, 0.f);
            #pragma unroll
            for (int it = 0; it < 4; it++) {
                int j = t + it * 512;            // 2048 float4s
                int col = j >> 4, q = j & 15;
                int gc = kt128 + col;
                stage4[j] = (gc < nv) ? e4[colid_s[gc] * 16 + q] : z4;
            }
            __syncthreads();
            const float* stage = (const float*)stage4;
            #pragma unroll
            for (int it = 0; it < 2; it++) {
                int j = t + it * 512;            // 1024 frag uint4s
                int lane = j & 31;
                int g = lane >> 2, tig = lane & 3;
                int kt = (j >> 5) & 3;
                int cc = (j >> 7) & 7;
                int k0 = kt * 16 + tig * 2;
                const float* e0 = stage + (cc * 16 + g) * 64;
                const float* e1 = e0 + 8 * 64;
                uint4 v;
                v.x = pk2(e0[k0], e0[k0 + 1]);
                v.y = pk2(e0[k0 + 8], e0[k0 + 9]);
                v.z = pk2(e1[k0], e1[k0 + 1]);
                v.w = pk2(e1[k0 + 8], e1[k0 + 9]);
                g_Bfrag4[ktile * 1024 + j] = v;
            }
        }
    } else if (cta < 166) {
        // ---- A fragments, one m-tile per CTA: stage coalesced, pack ----
        nv = local_nv(log_mask);
        int mt = cta - 116;                      // 0..49
        float4* stage4 = (float4*)(sm + 8192);
        const float4* p4 = (const float4*)prec;
        #pragma unroll
        for (int it = 0; it < 4; it++) {
            int j = t + it * 512;                // 2048 float4s, coalesced
            stage4[j] = p4[mt * 2048 + j];
        }
        __syncthreads();
        const float* stage = (const float*)stage4;
        #pragma unroll
        for (int it = 0; it < 2; it++) {
            int j = t + it * 512;
            int lane = j & 31;
            int g = lane >> 2, tig = lane & 3;
            int kt = (j >> 5) & 3;
            int b16 = (j >> 7) & 7;
            int k0 = kt * 16 + tig * 2;
            const float* ar = stage + (b16 * 16 + g) * 64;
            const float* ar8 = ar + 8 * 64;
            uint4 v;
            v.x = pk2(ar[k0] * LOG2E, ar[k0 + 1] * LOG2E);
            v.y = pk2(ar8[k0] * LOG2E, ar8[k0 + 1] * LOG2E);
            v.z = pk2(ar[k0 + 8] * LOG2E, ar[k0 + 9] * LOG2E);
            v.w = pk2(ar8[k0 + 8] * LOG2E, ar8[k0 + 9] * LOG2E);
            g_Afrag4[mt * 1024 + j] = v;
        }
    } else {
        // ---- target logits (exact fp32), 130 CTAs over 51200 slots ----
        nv = local_nv(log_mask);
        for (int slot = (cta - 166) * 512 + t; slot < NROW * 8; slot += 130 * 512) {
            int r = slot >> 3, sub = slot & 7;
            int i = r / LSEQ, j = r - i * LSEQ;
            int pos = j + 1;
            int valid = (pos == LSEQ) ? 1 : (log_mask[i * LSEQ + pos] != 0);
            int tc = i * LP1 + pos;
            const float4* p4 = (const float4*)(prec + r * DIM);
            const float4* e4 = (const float4*)(embs + tc * DIM);
            float4 a0 = p4[sub], b0 = e4[sub], a1 = p4[sub + 8], b1 = e4[sub + 8];
            float s = a0.x * b0.x + a0.y * b0.y + a0.z * b0.z + a0.w * b0.w
                    + a1.x * b1.x + a1.y * b1.y + a1.z * b1.z + a1.w * b1.w;
            s += __shfl_down_sync(0xffffffffu, s, 4);
            s += __shfl_down_sync(0xffffffffu, s, 2);
            s += __shfl_down_sync(0xffffffffu, s, 1);
            if (sub == 0) g_tgt[r] = valid ? (s - logf(pop[items[tc]])) : NEG10K;
        }
    }

    gsync(TOTAL_CTAS);

    // ======================= Phase C: sync-free GEMM + exp2 row-sums ==========
    // mt = cta % 50, rank = cta / 50; m-tiles 0..45: P=6 workers, 46..49: P=5.
    // A resident in smem; B fragments + keep from L2 (__ldg). No tile-loop
    // syncs. The two 16-row mti subtiles are processed SEQUENTIALLY so peak
    // live registers stay under the 64-reg cap (no spills).
    uint4* As4 = (uint4*)sm;                                   // 16 KB
    float* sred = sm + 4096;                                   // [4][128]

    const int w = t >> 5, lane = t & 31;
    const int g = lane >> 2, tig = lane & 3;
    const int rg = w >> 2;
    const int wcol = w & 3;
    const int mt_ = cta % NMT;
    const int rnk = cta / NMT;                 // 0..5
    const int P = (mt_ < 46) ? 6 : 5;
    const int m0 = mt_ * 128;
    const int T = (nv + 127) >> 7;
    const int ntiles = (T > rnk) ? ((T - rnk + P - 1) / P) : 0;

    // per-(mti,h) keep base pointers: batch row + column-group offset
    const float* kgp[2][2];
    #pragma unroll
    for (int mti = 0; mti < 2; mti++)
        #pragma unroll
        for (int h = 0; h < 2; h++) {
            int row = m0 + rg * 32 + mti * 16 + g + h * 8;
            kgp[mti][h] = g_keep + (size_t)(row / LSEQ) * NCOLP + wcol * 32 + 2 * tig;
        }

    float rs[4] = {0.f, 0.f, 0.f, 0.f};

    if (ntiles > 0) {
        // stage A once
        {
            const uint4* Ag = g_Afrag4 + (size_t)mt_ * 1024;
            cp16(smem_u32(sm) + t * 16, Ag + t);
            cp16(smem_u32(sm) + (t + 512) * 16, Ag + t + 512);
            CP_COMMIT();
            CP_WAIT0();
            __syncthreads();
        }

        for (int ti = 0; ti < ntiles; ti++) {
            const int ktile = rnk + ti * P;
            const uint4* bt = g_Bfrag4 + (size_t)ktile * 1024;
            const int koff = ktile * 128;

            #pragma unroll
            for (int cc2 = 0; cc2 < 2; cc2++) {
                const int cc = wcol * 2 + cc2;
                const uint4* bp = bt + cc * 128 + lane;
                uint4 b0 = __ldg(bp);
                uint4 b1 = __ldg(bp + 32);
                uint4 b2 = __ldg(bp + 64);
                uint4 b3 = __ldg(bp + 96);
                const int co = koff + cc2 * 16;

                #pragma unroll
                for (int mti = 0; mti < 2; mti++) {
                    // accumulators init with keep terms (-inf -> ex2 -> 0)
                    float2 k00 = *(const float2*)(kgp[mti][0] + co);
                    float2 k01 = *(const float2*)(kgp[mti][0] + co + 8);
                    float2 k10 = *(const float2*)(kgp[mti][1] + co);
                    float2 k11 = *(const float2*)(kgp[mti][1] + co + 8);
                    float c0[4] = {k00.x, k00.y, k10.x, k10.y};   // nt=0
                    float c1[4] = {k01.x, k01.y, k11.x, k11.y};   // nt=1

                    const uint4* ap = As4 + (rg * 2 + mti) * 128 + lane;
                    uint4 a;
                    a = ap[0];  mma16(c0, a, b0.x, b0.y); mma16(c1, a, b0.z, b0.w);
                    a = ap[32]; mma16(c0, a, b1.x, b1.y); mma16(c1, a, b1.z, b1.w);
                    a = ap[64]; mma16(c0, a, b2.x, b2.y); mma16(c1, a, b2.z, b2.w);
                    a = ap[96]; mma16(c0, a, b3.x, b3.y); mma16(c1, a, b3.z, b3.w);

                    rs[mti * 2 + 0] += (ex2f(c0[0]) + ex2f(c0[1]))
                                     + (ex2f(c1[0]) + ex2f(c1[1]));
                    rs[mti * 2 + 1] += (ex2f(c0[2]) + ex2f(c0[3]))
                                     + (ex2f(c1[2]) + ex2f(c1[3]));
                }
            }
        }
    }

    // in-CTA: reduce 4 tig lanes, then 4 col-group slices
    #pragma unroll
    for (int q = 0; q < 4; q++) {
        rs[q] += __shfl_xor_sync(0xffffffffu, rs[q], 1);
        rs[q] += __shfl_xor_sync(0xffffffffu, rs[q], 2);
    }
    __syncthreads();   // A smem / sred reuse ordering
    if (tig == 0) {
        #pragma unroll
        for (int mti = 0; mti < 2; mti++)
            #pragma unroll
            for (int h = 0; h < 2; h++)
                sred[wcol * 128 + rg * 32 + mti * 16 + h * 8 + g] = rs[mti * 2 + h];
    }
    __syncthreads();
    if (t < 128) {
        float s = (sred[t] + sred[t + 128]) + (sred[t + 256] + sred[t + 384]);
        g_partS[rnk * NROW + m0 + t] = s;
    }

    // ============== Phase D: per-m-tile finalize + deterministic total ==============
    __shared__ unsigned int s_lastm;
    __threadfence();
    __syncthreads();
    if (t == 0)
        s_lastm = (atomicAdd(&g_mctr[mt_], 1u) == (unsigned)(P - 1)) ? 1u : 0u;
    __syncthreads();
    if (s_lastm) {
        __threadfence();
        double num = 0.0, den = 0.0;
        if (t < 128) {
            int r = m0 + t;
            float S = 0.f;
            for (int c = 0; c < P; c++) S += g_partS[c * NROW + r];
            float tv = g_tgt[r];
            S += __expf(tv);
            float nll = (S > 0.f) ? (logf(S) - tv) : logf((float)NCOL);
            if (log_mask[r] != 0) { num = (double)nll; den = 1.0; }
        }
        #pragma unroll
        for (int o = 16; o > 0; o >>= 1) {
            num += __shfl_down_sync(0xffffffffu, num, o);
            den += __shfl_down_sync(0xffffffffu, den, o);
        }
        __shared__ double swn[16];
        __shared__ double swd[16];
        if (lane == 0) { swn[w] = num; swd[w] = den; }
        __syncthreads();
        if (t == 0) {
            double n = 0.0, d = 0.0;
            #pragma unroll
            for (int i = 0; i < 4; i++) { n += swn[i]; d += swd[i]; }
            g_rn[mt_] = n;
            g_rd[mt_] = d;
            __threadfence();
            if (atomicAdd(&g_fin, 1u) == NMT - 1) {
                __threadfence();
                double tn = 0.0, td = 0.0;
                for (int i = 0; i < NMT; i++) { tn += g_rn[i]; td += g_rd[i]; }
                out[0] = (float)(tn / td);
                // self-reset for next graph replay
                for (int i = 0; i < NMT; i++) g_mctr[i] = 0u;
                g_fin = 0u;
                g_bar = 0u;
            }
        }
    }
}

// ---------------------------------------------------------------------------
extern "C" void kernel_launch(void* const* d_in, const int* in_sizes, int n_in,
                              void* d_out, int out_size) {
    const float* prec  = (const float*)d_in[0];  // [6400, 64]
    const float* embs  = (const float*)d_in[1];  // [6464, 64]
    const float* pop   = (const float*)d_in[2];  // [100001]
    const int*   items = (const int*)d_in[3];    // [6464]
    const int*   lmask = (const int*)d_in[4];    // [64, 100]
    float* out = (float*)d_out;

    cudaFuncSetAttribute(mega_kernel, cudaFuncAttributeMaxDynamicSharedMemorySize,
                         SMEM_BYTES);

    mega_kernel<<<TOTAL_CTAS, 512, SMEM_BYTES>>>(lmask, items, pop, prec, embs, out);
}